// round 11
// baseline (speedup 1.0000x reference)
#include <cuda_runtime.h>
#include <cuda_fp16.h>
#include <math.h>
#include <stdint.h>

// ---------------- problem constants ----------------
#define BB 4
#define NN 4096
#define DD 1024
#define HH 16
#define HD 64
#define MTOT (BB*NN)          // 16384
#define N3D (3*DD)            // 3072
#define NSCALES 11

#define C0 0.4829629131445341f
#define C1 0.8365163037378079f
#define C2 0.2241438680420134f
#define C3 (-0.1294095225512604f)

// ---------------- scratch (device globals; allocation-free) ----------------
__device__ __half g_xh    [(size_t)MTOT * DD];      // 32 MB
__device__ __half g_qh    [(size_t)MTOT * DD];      // 32 MB
__device__ __half g_vh    [(size_t)MTOT * DD];      // 32 MB
__device__ float  g_ksq2  [(size_t)MTOT * HH * 2];  // 2 MB (2 partials/(row,head))
__device__ __half g_gateh [(size_t)MTOT * DD];      // 32 MB
__device__ __half g_fieldh[(size_t)BB*HH*HD*NN];    // [bh][d][n] 32 MB
__device__ __half g_acch  [(size_t)BB*HH*HD*NN];    // 32 MB
__device__ __half g_preh  [(size_t)MTOT * DD];      // 32 MB
__device__ __half g_wqkvT [(size_t)N3D * DD];       // 6 MB  [n][k]
__device__ __half g_wgateT[(size_t)DD * DD];
__device__ __half g_woutT [(size_t)DD * DD];
__device__ float  g_gains [NSCALES*HH];
__device__ float  g_sw    [2];
__device__ float  g_coup  [HH*HH];

// ---------------- helpers ----------------
__device__ __forceinline__ void cpa16(uint32_t s, const void* g) {
    asm volatile("cp.async.cg.shared.global [%0], [%1], 16;\n" :: "r"(s), "l"(g));
}
__device__ __forceinline__ void mma16816(float* d, const uint32_t* a, const uint32_t* b) {
    asm volatile(
        "mma.sync.aligned.m16n8k16.row.col.f32.f16.f16.f32 "
        "{%0,%1,%2,%3}, {%4,%5,%6,%7}, {%8,%9}, {%0,%1,%2,%3};\n"
        : "+f"(d[0]), "+f"(d[1]), "+f"(d[2]), "+f"(d[3])
        : "r"(a[0]), "r"(a[1]), "r"(a[2]), "r"(a[3]), "r"(b[0]), "r"(b[1]));
}
__device__ __forceinline__ void ldsm_x4(uint32_t& r0, uint32_t& r1, uint32_t& r2, uint32_t& r3,
                                        uint32_t addr) {
    asm volatile("ldmatrix.sync.aligned.m8n8.x4.shared.b16 {%0,%1,%2,%3}, [%4];"
                 : "=r"(r0), "=r"(r1), "=r"(r2), "=r"(r3) : "r"(addr));
}

// ---------------- K0: tiny prep ----------------
__global__ void prep_kernel(const float* __restrict__ scale_gain,
                            const float* __restrict__ skip_w,
                            const float* __restrict__ coupling) {
    int t = threadIdx.x;
    if (t < HH) {
        float m = -1e30f;
        for (int j = 0; j < NSCALES; j++) m = fmaxf(m, scale_gain[j*HH + t]);
        float e[NSCALES]; float s = 0.f;
        for (int j = 0; j < NSCALES; j++) { e[j] = expf(scale_gain[j*HH + t] - m); s += e[j]; }
        for (int j = 0; j < NSCALES; j++) g_gains[j*HH + t] = e[j] / s;
        float m2 = -1e30f;
        for (int j = 0; j < HH; j++) m2 = fmaxf(m2, coupling[t*HH + j]);
        float e2[HH]; float s2 = 0.f;
        for (int j = 0; j < HH; j++) { e2[j] = expf(coupling[t*HH + j] - m2); s2 += e2[j]; }
        for (int j = 0; j < HH; j++) g_coup[t*HH + j] = e2[j] / s2;
    }
    if (t < 2) g_sw[t] = 1.f / (1.f + expf(-skip_w[t]));
}

// ---------------- weight transpose to half: Wt[n][k] = (half)W[k][n] --------
__global__ __launch_bounds__(256)
void wtrans_kernel(const float* __restrict__ W, __half* __restrict__ Wt,
                   int K, int Nw) {
    __shared__ float s[32][33];
    int n0 = blockIdx.x * 32, k0 = blockIdx.y * 32;
    int tx = threadIdx.x & 31, ty = threadIdx.x >> 5;
    #pragma unroll
    for (int i = 0; i < 32; i += 8)
        s[ty + i][tx] = W[(size_t)(k0 + ty + i) * Nw + n0 + tx];
    __syncthreads();
    #pragma unroll
    for (int i = 0; i < 32; i += 8)
        Wt[(size_t)(n0 + ty + i) * K + k0 + tx] = __float2half_rn(s[tx][ty + i]);
}

// ---------------- x -> half ----------------
__global__ __launch_bounds__(256)
void tohalf_kernel(const float* __restrict__ in, __half* __restrict__ out) {
    size_t i = (size_t)blockIdx.x * 256 + threadIdx.x;
    float4 v = reinterpret_cast<const float4*>(in)[i];
    __half2 h01 = __floats2half2_rn(v.x, v.y);
    __half2 h23 = __floats2half2_rn(v.z, v.w);
    uint2 u = make_uint2(*(uint32_t*)&h01, *(uint32_t*)&h23);
    reinterpret_cast<uint2*>(out)[i] = u;
}

// ===== fp16 mma.sync GEMM with ldmatrix feeds: C = A[M,K] @ Bt[N,K]^T + bias
// BM=BN=128, BK=64, 256 threads, 8 warps (2x4), warp tile 64x32, 3-stage.
#define STG_B 32768
#define NSTAGE 3
#define GSMEM (NSTAGE*STG_B)   // 98304 bytes

// MODE 0: C fp32 (+sigmoid if ACT). MODE 1: qkv split:
//   col<1024 -> g_qh half ; 1024..2047 -> k: sum-of-squares partials only;
//   >=2048 -> g_vh half.  MODE 2: sigmoid -> g_gateh half.
template<int ACT, int MODE>
__global__ __launch_bounds__(256)
void mma_gemm(const __half* __restrict__ A,
              const __half* __restrict__ Bt,
              const float* __restrict__ bias,
              float* __restrict__ C, int ldc, int K) {
    extern __shared__ char smem[];
    const int tid  = threadIdx.x;
    const int lane = tid & 31;
    const int warp = tid >> 5;
    const int row0 = blockIdx.y * 128;
    const int col0 = blockIdx.x * 128;
    const int wr0  = (warp >> 2) * 64;
    const int wc0  = (warp & 3) * 32;
    const int lq   = lane >> 2;
    const int lr   = lane & 3;

    uint32_t sbase;
    asm("{ .reg .u64 t; cvta.to.shared.u64 t, %1; cvt.u32.u64 %0, t; }"
        : "=r"(sbase) : "l"((const void*)smem));

    float acc[4][4][4];
    #pragma unroll
    for (int r = 0; r < 4; r++)
        #pragma unroll
        for (int c = 0; c < 4; c++)
            #pragma unroll
            for (int e = 0; e < 4; e++) acc[r][c][e] = 0.f;

    auto load_stage = [&](int s, int kt) {
        uint32_t abase = sbase + s * STG_B;
        uint32_t bbase = abase + 16384;
        #pragma unroll
        for (int i = 0; i < 4; i++) {
            int c = tid + i * 256;
            int r = c >> 3, cc = c & 7;
            cpa16(abase + r * 128 + (((cc ^ r) & 7) << 4),
                  A + (size_t)(row0 + r) * K + kt * 64 + cc * 8);
        }
        #pragma unroll
        for (int i = 0; i < 4; i++) {
            int c = tid + i * 256;
            int r = c >> 3, cc = c & 7;
            cpa16(bbase + r * 128 + (((cc ^ r) & 7) << 4),
                  Bt + (size_t)(col0 + r) * K + kt * 64 + cc * 8);
        }
        asm volatile("cp.async.commit_group;\n");
    };

    const int KT = K >> 6;              // BK = 64
    load_stage(0, 0);
    load_stage(1, 1);

    const int aRowL = lane & 15;
    const int aCkL  = lane >> 4;
    const int bRowL = (lane & 7) + ((lane >> 4) << 3);
    const int bCkL  = (lane >> 3) & 1;

    for (int kt = 0; kt < KT; kt++) {
        if (kt + 1 < KT) asm volatile("cp.async.wait_group 1;\n");
        else             asm volatile("cp.async.wait_group 0;\n");
        __syncthreads();
        if (kt + 2 < KT) load_stage((kt + 2) % NSTAGE, kt + 2);

        uint32_t sA = sbase + (kt % NSTAGE) * STG_B;
        uint32_t sB = sA + 16384;
        #pragma unroll
        for (int kk = 0; kk < 64; kk += 16) {
            const int ck = kk >> 3;
            uint32_t af[4][4], bf[4][2];
            const int cA = ck + aCkL;
            #pragma unroll
            for (int rt = 0; rt < 4; rt++) {
                int r = wr0 + rt * 16 + aRowL;
                ldsm_x4(af[rt][0], af[rt][1], af[rt][2], af[rt][3],
                        sA + r * 128 + (((cA ^ r) & 7) << 4));
            }
            const int cB = ck + bCkL;
            #pragma unroll
            for (int p = 0; p < 2; p++) {
                int r = wc0 + p * 16 + bRowL;
                uint32_t m0, m1, m2, m3;
                ldsm_x4(m0, m1, m2, m3, sB + r * 128 + (((cB ^ r) & 7) << 4));
                bf[2*p][0] = m0; bf[2*p][1] = m1;
                bf[2*p+1][0] = m2; bf[2*p+1][1] = m3;
            }
            #pragma unroll
            for (int r = 0; r < 4; r++)
                #pragma unroll
                for (int c = 0; c < 4; c++)
                    mma16816(acc[r][c], af[r], bf[c]);
        }
        __syncthreads();
    }

    // ---- epilogue ----
    if (MODE == 1 && col0 >= DD && col0 < 2*DD) {
        // k columns: reduce sum of squares; k is never stored.
        const int head = (col0 - DD + wc0) >> 6;      // uniform per warp
        const int part = (wc0 >> 5) & 1;              // which 32-col half of the head
        #pragma unroll
        for (int r = 0; r < 4; r++) {
            int row = row0 + wr0 + r*16 + lq;
            float s0 = 0.f, s1 = 0.f;
            #pragma unroll
            for (int c = 0; c < 4; c++) {
                int col = col0 + wc0 + c*8 + lr*2;
                float2 b2 = *reinterpret_cast<const float2*>(bias + col);
                float v0 = acc[r][c][0] + b2.x, v1 = acc[r][c][1] + b2.y;
                float v2 = acc[r][c][2] + b2.x, v3 = acc[r][c][3] + b2.y;
                s0 += v0*v0 + v1*v1;
                s1 += v2*v2 + v3*v3;
            }
            s0 += __shfl_xor_sync(0xffffffffu, s0, 1);
            s0 += __shfl_xor_sync(0xffffffffu, s0, 2);
            s1 += __shfl_xor_sync(0xffffffffu, s1, 1);
            s1 += __shfl_xor_sync(0xffffffffu, s1, 2);
            if (lr == 0) {
                g_ksq2[((size_t)row*HH + head)*2 + part]     = s0;
                g_ksq2[((size_t)(row+8)*HH + head)*2 + part] = s1;
            }
        }
    } else {
        #pragma unroll
        for (int r = 0; r < 4; r++) {
            int row = row0 + wr0 + r*16 + lq;
            #pragma unroll
            for (int c = 0; c < 4; c++) {
                int col = col0 + wc0 + c*8 + lr*2;
                float2 b2 = *reinterpret_cast<const float2*>(bias + col);
                float v0 = acc[r][c][0] + b2.x, v1 = acc[r][c][1] + b2.y;
                float v2 = acc[r][c][2] + b2.x, v3 = acc[r][c][3] + b2.y;
                if (ACT) {
                    v0 = 1.f/(1.f + __expf(-v0)); v1 = 1.f/(1.f + __expf(-v1));
                    v2 = 1.f/(1.f + __expf(-v2)); v3 = 1.f/(1.f + __expf(-v3));
                }
                if (MODE == 0) {
                    *reinterpret_cast<float2*>(C + (size_t)row*ldc + col)     = make_float2(v0, v1);
                    *reinterpret_cast<float2*>(C + (size_t)(row+8)*ldc + col) = make_float2(v2, v3);
                } else {
                    __half2 h0 = __floats2half2_rn(v0, v1);
                    __half2 h1 = __floats2half2_rn(v2, v3);
                    if (MODE == 2) {
                        *(uint32_t*)(g_gateh + (size_t)row*DD + col)     = *(uint32_t*)&h0;
                        *(uint32_t*)(g_gateh + (size_t)(row+8)*DD + col) = *(uint32_t*)&h1;
                    } else if (col0 < DD) {   // q
                        *(uint32_t*)(g_qh + (size_t)row*DD + col)     = *(uint32_t*)&h0;
                        *(uint32_t*)(g_qh + (size_t)(row+8)*DD + col) = *(uint32_t*)&h1;
                    } else {                  // v
                        int cc = col - 2*DD;
                        *(uint32_t*)(g_vh + (size_t)row*DD + cc)     = *(uint32_t*)&h0;
                        *(uint32_t*)(g_vh + (size_t)(row+8)*DD + cc) = *(uint32_t*)&h1;
                    }
                }
            }
        }
    }
}

// ---------------- field[bh][d][n] = v * ||k|| -------------------------------
__global__ __launch_bounds__(256)
void field_kernel() {
    const int bh = blockIdx.y;
    const int b  = bh >> 4, h = bh & 15;
    const int n0 = blockIdx.x * 32;
    __shared__ float s_kmag[32];
    __shared__ float s_t[64][33];
    const int tid = threadIdx.x;
    if (tid < 32) {
        const float* kp = g_ksq2 + ((size_t)(b*NN + n0 + tid)*HH + h)*2;
        s_kmag[tid] = sqrtf(kp[0] + kp[1]);
    }
    __syncthreads();
    for (int idx = tid; idx < 2048; idx += 256) {
        int nl = idx >> 6, d = idx & 63;
        float v = __half2float(g_vh[(size_t)(b*NN + n0 + nl)*DD + h*HD + d]);
        s_t[d][nl] = v * s_kmag[nl];
    }
    __syncthreads();
    for (int idx = tid; idx < 2048; idx += 256) {
        int d = idx >> 5, nl = idx & 31;
        g_fieldh[((size_t)bh*HD + d)*NN + n0 + nl] = __float2half_rn(s_t[d][nl]);
    }
}

// ---------------- pyramid + sparse skips ------------------------------------
__global__ __launch_bounds__(256)
void pyramid_kernel() {
    const int r = blockIdx.x;               // bh*64 + d
    const int h = (r >> 6) & 15;
    const __half* row_g = g_fieldh + (size_t)r * NN;
    __shared__ float s_row[NN];
    __shared__ float s_acc[NN];
    const int tid = threadIdx.x;
    for (int i = tid; i < NN/8; i += 256) {
        uint4 u = reinterpret_cast<const uint4*>(row_g)[i];
        const __half2* hp = reinterpret_cast<const __half2*>(&u);
        float* dst = s_row + i*8;
        #pragma unroll
        for (int e = 0; e < 4; e++) {
            float2 f = __half22float2(hp[e]);
            dst[e*2] = f.x; dst[e*2+1] = f.y;
        }
    }
    float g[NSCALES];
    #pragma unroll
    for (int j = 0; j < NSCALES; j++) g[j] = g_gains[j*HH + h];
    const float sw0 = g_sw[0], sw1 = g_sw[1];
    __syncthreads();
    for (int n = tid; n < NN; n += 256) {
        float acc = 0.f;
        #pragma unroll
        for (int j = 0; j < NSCALES; j++) {
            int d = 1 << j;
            float y = C3 * s_row[n];
            if (n >= d)     y += C2 * s_row[n - d];
            if (n >= 2*d)   y += C1 * s_row[n - 2*d];
            if (n >= 3*d)   y += C0 * s_row[n - 3*d];
            acc += g[j] * y;
        }
        s_acc[n] = acc;
    }
    __syncthreads();
    __half* out_g = g_acch + (size_t)r * NN;
    for (int i = tid; i < NN/8; i += 256) {
        uint4 u;
        __half2* hp = reinterpret_cast<__half2*>(&u);
        #pragma unroll
        for (int e = 0; e < 4; e++) {
            int n = i*8 + e*2;
            float v0 = s_acc[n];
            float v1 = s_acc[n+1];
            if (n   >= 512)  v0 += sw0 * s_acc[n - 512];
            if (n+1 >= 512)  v1 += sw0 * s_acc[n+1 - 512];
            if (n   >= 1024) v0 += sw1 * s_acc[n - 1024];
            if (n+1 >= 1024) v1 += sw1 * s_acc[n+1 - 1024];
            hp[e] = __floats2half2_rn(v0, v1);
        }
        reinterpret_cast<uint4*>(out_g)[i] = u;
    }
}

// ------- fused coupling + transpose-back + gate + half-convert --------------
#define CGP 1040
#define CGSMEM (HH*CGP*4)   // 66560 bytes
__global__ __launch_bounds__(256)
void cg_kernel() {
    extern __shared__ float s[];
    __shared__ float sc[HH*HH];
    const int b  = blockIdx.y;
    const int n0 = blockIdx.x * 16;
    const int tid = threadIdx.x;
    if (tid < HH*HH) sc[tid] = g_coup[tid];
    for (int idx = tid; idx < 2048; idx += 256) {
        int row = idx >> 1, c8 = idx & 1;
        int j = row >> 6, d = row & 63;
        uint4 u = *reinterpret_cast<const uint4*>(
            g_acch + ((size_t)(b*HH + j)*HD + d)*NN + n0 + c8*8);
        const __half2* hp = reinterpret_cast<const __half2*>(&u);
        float* sp = s + j*CGP + d;
        #pragma unroll
        for (int e = 0; e < 4; e++) {
            float2 f = __half22float2(hp[e]);
            sp[(c8*8 + e*2)*64]     = f.x;
            sp[(c8*8 + e*2 + 1)*64] = f.y;
        }
    }
    __syncthreads();
    #pragma unroll
    for (int t = 0; t < 4; t++) {
        int p  = tid + 256*t;       // nl*64 + d
        int d  = p & 63, nl = p >> 6;
        float in[HH];
        #pragma unroll
        for (int j = 0; j < HH; j++) in[j] = s[j*CGP + nl*64 + d];
        #pragma unroll
        for (int h = 0; h < HH; h++) {
            float o = 0.f;
            #pragma unroll
            for (int j = 0; j < HH; j++) o += sc[h*HH + j] * in[j];
            size_t addr = ((size_t)(b*NN + n0 + nl))*DD + h*HD + d;
            float gt = __half2float(g_gateh[addr]);
            g_preh[addr] = __float2half_rn(o * gt);
        }
    }
}

// ---------------- launch ----------------------------------------------------
extern "C" void kernel_launch(void* const* d_in, const int* in_sizes, int n_in,
                              void* d_out, int out_size) {
    const float* x          = (const float*)d_in[0];
    const float* Wqkv       = (const float*)d_in[1];
    const float* bqkv       = (const float*)d_in[2];
    const float* Wout       = (const float*)d_in[3];
    const float* bout       = (const float*)d_in[4];
    const float* Wgate      = (const float*)d_in[5];
    const float* bgate      = (const float*)d_in[6];
    const float* scale_gain = (const float*)d_in[7];
    const float* skip_w     = (const float*)d_in[8];
    const float* coupling   = (const float*)d_in[9];
    float* out = (float*)d_out;

    __half *p_xh, *p_qh, *p_preh, *p_wqkvT, *p_wgateT, *p_woutT;
    cudaGetSymbolAddress((void**)&p_xh,     g_xh);
    cudaGetSymbolAddress((void**)&p_qh,     g_qh);
    cudaGetSymbolAddress((void**)&p_preh,   g_preh);
    cudaGetSymbolAddress((void**)&p_wqkvT,  g_wqkvT);
    cudaGetSymbolAddress((void**)&p_wgateT, g_wgateT);
    cudaGetSymbolAddress((void**)&p_woutT,  g_woutT);

    cudaFuncSetAttribute(mma_gemm<0,1>, cudaFuncAttributeMaxDynamicSharedMemorySize, GSMEM);
    cudaFuncSetAttribute(mma_gemm<1,2>, cudaFuncAttributeMaxDynamicSharedMemorySize, GSMEM);
    cudaFuncSetAttribute(mma_gemm<0,0>, cudaFuncAttributeMaxDynamicSharedMemorySize, GSMEM);
    cudaFuncSetAttribute(cg_kernel,     cudaFuncAttributeMaxDynamicSharedMemorySize, CGSMEM);

    prep_kernel<<<1, 32>>>(scale_gain, skip_w, coupling);

    wtrans_kernel<<<dim3(N3D/32, DD/32), 256>>>(Wqkv,  p_wqkvT,  DD, N3D);
    wtrans_kernel<<<dim3(DD/32,  DD/32), 256>>>(Wgate, p_wgateT, DD, DD);
    wtrans_kernel<<<dim3(DD/32,  DD/32), 256>>>(Wout,  p_woutT,  DD, DD);
    tohalf_kernel<<<(MTOT*DD/4)/256, 256>>>(x, p_xh);

    // GEMM1: qkv = x @ Wqkv + bqkv  (split: q->half, k->sumsq partials, v->half)
    mma_gemm<0,1><<<dim3(N3D/128, MTOT/128), 256, GSMEM>>>(
        p_xh, p_wqkvT, bqkv, nullptr, 0, DD);
    // GEMM2: gate = sigmoid(q @ Wgate + bgate) -> half
    mma_gemm<1,2><<<dim3(DD/128, MTOT/128), 256, GSMEM>>>(
        p_qh, p_wgateT, bgate, nullptr, 0, DD);

    field_kernel  <<<dim3(NN/32, BB*HH), 256>>>();
    pyramid_kernel<<<BB*HH*HD, 256>>>();
    cg_kernel     <<<dim3(NN/16, BB), 256, CGSMEM>>>();

    // GEMM3: out = pre @ Wout + bout
    mma_gemm<0,0><<<dim3(DD/128, MTOT/128), 256, GSMEM>>>(
        p_preh, p_woutT, bout, out, DD, DD);
}

// round 12
// speedup vs baseline: 1.4042x; 1.4042x over previous
#include <cuda_runtime.h>
#include <cuda_fp16.h>
#include <math.h>
#include <stdint.h>

// ---------------- problem constants ----------------
#define BB 4
#define NN 4096
#define DD 1024
#define HH 16
#define HD 64
#define MTOT (BB*NN)          // 16384
#define N3D (3*DD)            // 3072
#define NSCALES 11

#define C0 0.4829629131445341f
#define C1 0.8365163037378079f
#define C2 0.2241438680420134f
#define C3 (-0.1294095225512604f)

// ---------------- scratch (device globals; allocation-free) ----------------
__device__ __half g_xh    [(size_t)MTOT * DD];      // 32 MB
__device__ __half g_qh    [(size_t)MTOT * DD];      // 32 MB
__device__ __half g_vh    [(size_t)MTOT * DD];      // 32 MB
__device__ float  g_ksq2  [(size_t)MTOT * HH * 2];  // 2 MB (2 partials/(row,head))
__device__ __half g_gateh [(size_t)MTOT * DD];      // 32 MB
__device__ __half g_fieldh[(size_t)BB*HH*HD*NN];    // [bh][d][n] 32 MB
__device__ __half g_acch  [(size_t)BB*HH*HD*NN];    // 32 MB
__device__ __half g_preh  [(size_t)MTOT * DD];      // 32 MB
__device__ __half g_wqkvT [(size_t)N3D * DD];       // 6 MB  [n][k]
__device__ __half g_wgateT[(size_t)DD * DD];
__device__ __half g_woutT [(size_t)DD * DD];
__device__ float  g_gains [NSCALES*HH];
__device__ float  g_sw    [2];
__device__ float  g_coup  [HH*HH];

// ---------------- helpers ----------------
__device__ __forceinline__ void cpa16(uint32_t s, const void* g) {
    asm volatile("cp.async.cg.shared.global [%0], [%1], 16;\n" :: "r"(s), "l"(g));
}
__device__ __forceinline__ void mma16816(float* d, const uint32_t* a, const uint32_t* b) {
    asm volatile(
        "mma.sync.aligned.m16n8k16.row.col.f32.f16.f16.f32 "
        "{%0,%1,%2,%3}, {%4,%5,%6,%7}, {%8,%9}, {%0,%1,%2,%3};\n"
        : "+f"(d[0]), "+f"(d[1]), "+f"(d[2]), "+f"(d[3])
        : "r"(a[0]), "r"(a[1]), "r"(a[2]), "r"(a[3]), "r"(b[0]), "r"(b[1]));
}
__device__ __forceinline__ void ldsm_x4(uint32_t& r0, uint32_t& r1, uint32_t& r2, uint32_t& r3,
                                        uint32_t addr) {
    asm volatile("ldmatrix.sync.aligned.m8n8.x4.shared.b16 {%0,%1,%2,%3}, [%4];"
                 : "=r"(r0), "=r"(r1), "=r"(r2), "=r"(r3) : "r"(addr));
}

// ---------------- K0: tiny prep ----------------
__global__ void prep_kernel(const float* __restrict__ scale_gain,
                            const float* __restrict__ skip_w,
                            const float* __restrict__ coupling) {
    int t = threadIdx.x;
    if (t < HH) {
        float m = -1e30f;
        for (int j = 0; j < NSCALES; j++) m = fmaxf(m, scale_gain[j*HH + t]);
        float e[NSCALES]; float s = 0.f;
        for (int j = 0; j < NSCALES; j++) { e[j] = expf(scale_gain[j*HH + t] - m); s += e[j]; }
        for (int j = 0; j < NSCALES; j++) g_gains[j*HH + t] = e[j] / s;
        float m2 = -1e30f;
        for (int j = 0; j < HH; j++) m2 = fmaxf(m2, coupling[t*HH + j]);
        float e2[HH]; float s2 = 0.f;
        for (int j = 0; j < HH; j++) { e2[j] = expf(coupling[t*HH + j] - m2); s2 += e2[j]; }
        for (int j = 0; j < HH; j++) g_coup[t*HH + j] = e2[j] / s2;
    }
    if (t < 2) g_sw[t] = 1.f / (1.f + expf(-skip_w[t]));
}

// ---------------- weight transpose to half: Wt[n][k] = (half)W[k][n] --------
__global__ __launch_bounds__(256)
void wtrans_kernel(const float* __restrict__ W, __half* __restrict__ Wt,
                   int K, int Nw) {
    __shared__ float s[32][33];
    int n0 = blockIdx.x * 32, k0 = blockIdx.y * 32;
    int tx = threadIdx.x & 31, ty = threadIdx.x >> 5;
    #pragma unroll
    for (int i = 0; i < 32; i += 8)
        s[ty + i][tx] = W[(size_t)(k0 + ty + i) * Nw + n0 + tx];
    __syncthreads();
    #pragma unroll
    for (int i = 0; i < 32; i += 8)
        Wt[(size_t)(n0 + ty + i) * K + k0 + tx] = __float2half_rn(s[tx][ty + i]);
}

// ---------------- x -> half ----------------
__global__ __launch_bounds__(256)
void tohalf_kernel(const float* __restrict__ in, __half* __restrict__ out) {
    size_t i = (size_t)blockIdx.x * 256 + threadIdx.x;
    float4 v = reinterpret_cast<const float4*>(in)[i];
    __half2 h01 = __floats2half2_rn(v.x, v.y);
    __half2 h23 = __floats2half2_rn(v.z, v.w);
    uint2 u = make_uint2(*(uint32_t*)&h01, *(uint32_t*)&h23);
    reinterpret_cast<uint2*>(out)[i] = u;
}

// ===== fp16 mma.sync GEMM with ldmatrix feeds: C = A[M,K] @ Bt[N,K]^T + bias
// BM=BN=128, BK=64, 256 threads, 8 warps (2x4), warp tile 64x32, 3-stage.
#define STG_B 32768
#define NSTAGE 3
#define GSMEM (NSTAGE*STG_B)   // 98304 bytes

// MODE 0: C fp32 (+sigmoid if ACT). MODE 1: qkv split:
//   col<1024 -> g_qh half ; 1024..2047 -> k: sum-of-squares partials only;
//   >=2048 -> g_vh half.  MODE 2: sigmoid -> g_gateh half.
template<int ACT, int MODE>
__global__ __launch_bounds__(256)
void mma_gemm(const __half* __restrict__ A,
              const __half* __restrict__ Bt,
              const float* __restrict__ bias,
              float* __restrict__ C, int ldc, int K) {
    extern __shared__ char smem[];
    const int tid  = threadIdx.x;
    const int lane = tid & 31;
    const int warp = tid >> 5;
    const int row0 = blockIdx.y * 128;
    const int col0 = blockIdx.x * 128;
    const int wr0  = (warp >> 2) * 64;
    const int wc0  = (warp & 3) * 32;
    const int lq   = lane >> 2;
    const int lr   = lane & 3;

    uint32_t sbase;
    asm("{ .reg .u64 t; cvta.to.shared.u64 t, %1; cvt.u32.u64 %0, t; }"
        : "=r"(sbase) : "l"((const void*)smem));

    float acc[4][4][4];
    #pragma unroll
    for (int r = 0; r < 4; r++)
        #pragma unroll
        for (int c = 0; c < 4; c++)
            #pragma unroll
            for (int e = 0; e < 4; e++) acc[r][c][e] = 0.f;

    auto load_stage = [&](int s, int kt) {
        uint32_t abase = sbase + s * STG_B;
        uint32_t bbase = abase + 16384;
        #pragma unroll
        for (int i = 0; i < 4; i++) {
            int c = tid + i * 256;
            int r = c >> 3, cc = c & 7;
            cpa16(abase + r * 128 + (((cc ^ r) & 7) << 4),
                  A + (size_t)(row0 + r) * K + kt * 64 + cc * 8);
        }
        #pragma unroll
        for (int i = 0; i < 4; i++) {
            int c = tid + i * 256;
            int r = c >> 3, cc = c & 7;
            cpa16(bbase + r * 128 + (((cc ^ r) & 7) << 4),
                  Bt + (size_t)(col0 + r) * K + kt * 64 + cc * 8);
        }
        asm volatile("cp.async.commit_group;\n");
    };

    const int KT = K >> 6;              // BK = 64
    load_stage(0, 0);
    load_stage(1, 1);

    const int aRowL = lane & 15;
    const int aCkL  = lane >> 4;
    const int bRowL = (lane & 7) + ((lane >> 4) << 3);
    const int bCkL  = (lane >> 3) & 1;

    for (int kt = 0; kt < KT; kt++) {
        if (kt + 1 < KT) asm volatile("cp.async.wait_group 1;\n");
        else             asm volatile("cp.async.wait_group 0;\n");
        __syncthreads();
        if (kt + 2 < KT) load_stage((kt + 2) % NSTAGE, kt + 2);

        uint32_t sA = sbase + (kt % NSTAGE) * STG_B;
        uint32_t sB = sA + 16384;
        #pragma unroll
        for (int kk = 0; kk < 64; kk += 16) {
            const int ck = kk >> 3;
            uint32_t af[4][4], bf[4][2];
            const int cA = ck + aCkL;
            #pragma unroll
            for (int rt = 0; rt < 4; rt++) {
                int r = wr0 + rt * 16 + aRowL;
                ldsm_x4(af[rt][0], af[rt][1], af[rt][2], af[rt][3],
                        sA + r * 128 + (((cA ^ r) & 7) << 4));
            }
            const int cB = ck + bCkL;
            #pragma unroll
            for (int p = 0; p < 2; p++) {
                int r = wc0 + p * 16 + bRowL;
                uint32_t m0, m1, m2, m3;
                ldsm_x4(m0, m1, m2, m3, sB + r * 128 + (((cB ^ r) & 7) << 4));
                bf[2*p][0] = m0; bf[2*p][1] = m1;
                bf[2*p+1][0] = m2; bf[2*p+1][1] = m3;
            }
            #pragma unroll
            for (int r = 0; r < 4; r++)
                #pragma unroll
                for (int c = 0; c < 4; c++)
                    mma16816(acc[r][c], af[r], bf[c]);
        }
        __syncthreads();
    }

    // ---- epilogue ----
    if (MODE == 1 && col0 >= DD && col0 < 2*DD) {
        // k columns: reduce sum of squares; k is never stored.
        const int head = (col0 - DD + wc0) >> 6;      // uniform per warp
        const int part = (wc0 >> 5) & 1;              // which 32-col half of the head
        #pragma unroll
        for (int r = 0; r < 4; r++) {
            int row = row0 + wr0 + r*16 + lq;
            float s0 = 0.f, s1 = 0.f;
            #pragma unroll
            for (int c = 0; c < 4; c++) {
                int col = col0 + wc0 + c*8 + lr*2;
                float2 b2 = *reinterpret_cast<const float2*>(bias + col);
                float v0 = acc[r][c][0] + b2.x, v1 = acc[r][c][1] + b2.y;
                float v2 = acc[r][c][2] + b2.x, v3 = acc[r][c][3] + b2.y;
                s0 += v0*v0 + v1*v1;
                s1 += v2*v2 + v3*v3;
            }
            s0 += __shfl_xor_sync(0xffffffffu, s0, 1);
            s0 += __shfl_xor_sync(0xffffffffu, s0, 2);
            s1 += __shfl_xor_sync(0xffffffffu, s1, 1);
            s1 += __shfl_xor_sync(0xffffffffu, s1, 2);
            if (lr == 0) {
                g_ksq2[((size_t)row*HH + head)*2 + part]     = s0;
                g_ksq2[((size_t)(row+8)*HH + head)*2 + part] = s1;
            }
        }
    } else {
        #pragma unroll
        for (int r = 0; r < 4; r++) {
            int row = row0 + wr0 + r*16 + lq;
            #pragma unroll
            for (int c = 0; c < 4; c++) {
                int col = col0 + wc0 + c*8 + lr*2;
                float2 b2 = *reinterpret_cast<const float2*>(bias + col);
                float v0 = acc[r][c][0] + b2.x, v1 = acc[r][c][1] + b2.y;
                float v2 = acc[r][c][2] + b2.x, v3 = acc[r][c][3] + b2.y;
                if (ACT) {
                    v0 = 1.f/(1.f + __expf(-v0)); v1 = 1.f/(1.f + __expf(-v1));
                    v2 = 1.f/(1.f + __expf(-v2)); v3 = 1.f/(1.f + __expf(-v3));
                }
                if (MODE == 0) {
                    *reinterpret_cast<float2*>(C + (size_t)row*ldc + col)     = make_float2(v0, v1);
                    *reinterpret_cast<float2*>(C + (size_t)(row+8)*ldc + col) = make_float2(v2, v3);
                } else {
                    __half2 h0 = __floats2half2_rn(v0, v1);
                    __half2 h1 = __floats2half2_rn(v2, v3);
                    if (MODE == 2) {
                        *(uint32_t*)(g_gateh + (size_t)row*DD + col)     = *(uint32_t*)&h0;
                        *(uint32_t*)(g_gateh + (size_t)(row+8)*DD + col) = *(uint32_t*)&h1;
                    } else if (col0 < DD) {   // q
                        *(uint32_t*)(g_qh + (size_t)row*DD + col)     = *(uint32_t*)&h0;
                        *(uint32_t*)(g_qh + (size_t)(row+8)*DD + col) = *(uint32_t*)&h1;
                    } else {                  // v
                        int cc = col - 2*DD;
                        *(uint32_t*)(g_vh + (size_t)row*DD + cc)     = *(uint32_t*)&h0;
                        *(uint32_t*)(g_vh + (size_t)(row+8)*DD + cc) = *(uint32_t*)&h1;
                    }
                }
            }
        }
    }
}

// ---------------- field[bh][d][n] = v * ||k|| -------------------------------
__global__ __launch_bounds__(256)
void field_kernel() {
    const int bh = blockIdx.y;
    const int b  = bh >> 4, h = bh & 15;
    const int n0 = blockIdx.x * 32;
    __shared__ float s_kmag[32];
    __shared__ float s_t[64][33];
    const int tid = threadIdx.x;
    if (tid < 32) {
        const float* kp = g_ksq2 + ((size_t)(b*NN + n0 + tid)*HH + h)*2;
        s_kmag[tid] = sqrtf(kp[0] + kp[1]);
    }
    __syncthreads();
    for (int idx = tid; idx < 2048; idx += 256) {
        int nl = idx >> 6, d = idx & 63;
        float v = __half2float(g_vh[(size_t)(b*NN + n0 + nl)*DD + h*HD + d]);
        s_t[d][nl] = v * s_kmag[nl];
    }
    __syncthreads();
    for (int idx = tid; idx < 2048; idx += 256) {
        int d = idx >> 5, nl = idx & 31;
        g_fieldh[((size_t)bh*HD + d)*NN + n0 + nl] = __float2half_rn(s_t[d][nl]);
    }
}

// ---------------- pyramid + sparse skips ------------------------------------
__global__ __launch_bounds__(256)
void pyramid_kernel() {
    const int r = blockIdx.x;               // bh*64 + d
    const int h = (r >> 6) & 15;
    const __half* row_g = g_fieldh + (size_t)r * NN;
    __shared__ float s_row[NN];
    __shared__ float s_acc[NN];
    const int tid = threadIdx.x;
    for (int i = tid; i < NN/8; i += 256) {
        uint4 u = reinterpret_cast<const uint4*>(row_g)[i];
        const __half2* hp = reinterpret_cast<const __half2*>(&u);
        float* dst = s_row + i*8;
        #pragma unroll
        for (int e = 0; e < 4; e++) {
            float2 f = __half22float2(hp[e]);
            dst[e*2] = f.x; dst[e*2+1] = f.y;
        }
    }
    float g[NSCALES];
    #pragma unroll
    for (int j = 0; j < NSCALES; j++) g[j] = g_gains[j*HH + h];
    const float sw0 = g_sw[0], sw1 = g_sw[1];
    __syncthreads();
    for (int n = tid; n < NN; n += 256) {
        float acc = 0.f;
        #pragma unroll
        for (int j = 0; j < NSCALES; j++) {
            int d = 1 << j;
            float y = C3 * s_row[n];
            if (n >= d)     y += C2 * s_row[n - d];
            if (n >= 2*d)   y += C1 * s_row[n - 2*d];
            if (n >= 3*d)   y += C0 * s_row[n - 3*d];
            acc += g[j] * y;
        }
        s_acc[n] = acc;
    }
    __syncthreads();
    __half* out_g = g_acch + (size_t)r * NN;
    for (int i = tid; i < NN/8; i += 256) {
        uint4 u;
        __half2* hp = reinterpret_cast<__half2*>(&u);
        #pragma unroll
        for (int e = 0; e < 4; e++) {
            int n = i*8 + e*2;
            float v0 = s_acc[n];
            float v1 = s_acc[n+1];
            if (n   >= 512)  v0 += sw0 * s_acc[n - 512];
            if (n+1 >= 512)  v1 += sw0 * s_acc[n+1 - 512];
            if (n   >= 1024) v0 += sw1 * s_acc[n - 1024];
            if (n+1 >= 1024) v1 += sw1 * s_acc[n+1 - 1024];
            hp[e] = __floats2half2_rn(v0, v1);
        }
        reinterpret_cast<uint4*>(out_g)[i] = u;
    }
}

// ------- fused coupling + transpose-back + gate + half-convert --------------
#define CGP 1040
#define CGSMEM (HH*CGP*4)   // 66560 bytes
__global__ __launch_bounds__(256)
void cg_kernel() {
    extern __shared__ float s[];
    __shared__ float sc[HH*HH];
    const int b  = blockIdx.y;
    const int n0 = blockIdx.x * 16;
    const int tid = threadIdx.x;
    if (tid < HH*HH) sc[tid] = g_coup[tid];
    for (int idx = tid; idx < 2048; idx += 256) {
        int row = idx >> 1, c8 = idx & 1;
        int j = row >> 6, d = row & 63;
        uint4 u = *reinterpret_cast<const uint4*>(
            g_acch + ((size_t)(b*HH + j)*HD + d)*NN + n0 + c8*8);
        const __half2* hp = reinterpret_cast<const __half2*>(&u);
        float* sp = s + j*CGP + d;
        #pragma unroll
        for (int e = 0; e < 4; e++) {
            float2 f = __half22float2(hp[e]);
            sp[(c8*8 + e*2)*64]     = f.x;
            sp[(c8*8 + e*2 + 1)*64] = f.y;
        }
    }
    __syncthreads();
    #pragma unroll
    for (int t = 0; t < 4; t++) {
        int p  = tid + 256*t;       // nl*64 + d
        int d  = p & 63, nl = p >> 6;
        float in[HH];
        #pragma unroll
        for (int j = 0; j < HH; j++) in[j] = s[j*CGP + nl*64 + d];
        #pragma unroll
        for (int h = 0; h < HH; h++) {
            float o = 0.f;
            #pragma unroll
            for (int j = 0; j < HH; j++) o += sc[h*HH + j] * in[j];
            size_t addr = ((size_t)(b*NN + n0 + nl))*DD + h*HD + d;
            float gt = __half2float(g_gateh[addr]);
            g_preh[addr] = __float2half_rn(o * gt);
        }
    }
}

// ---------------- launch ----------------------------------------------------
extern "C" void kernel_launch(void* const* d_in, const int* in_sizes, int n_in,
                              void* d_out, int out_size) {
    const float* x          = (const float*)d_in[0];
    const float* Wqkv       = (const float*)d_in[1];
    const float* bqkv       = (const float*)d_in[2];
    const float* Wout       = (const float*)d_in[3];
    const float* bout       = (const float*)d_in[4];
    const float* Wgate      = (const float*)d_in[5];
    const float* bgate      = (const float*)d_in[6];
    const float* scale_gain = (const float*)d_in[7];
    const float* skip_w     = (const float*)d_in[8];
    const float* coupling   = (const float*)d_in[9];
    float* out = (float*)d_out;

    __half *p_xh, *p_qh, *p_preh, *p_wqkvT, *p_wgateT, *p_woutT;
    cudaGetSymbolAddress((void**)&p_xh,     g_xh);
    cudaGetSymbolAddress((void**)&p_qh,     g_qh);
    cudaGetSymbolAddress((void**)&p_preh,   g_preh);
    cudaGetSymbolAddress((void**)&p_wqkvT,  g_wqkvT);
    cudaGetSymbolAddress((void**)&p_wgateT, g_wgateT);
    cudaGetSymbolAddress((void**)&p_woutT,  g_woutT);

    cudaFuncSetAttribute(mma_gemm<0,1>, cudaFuncAttributeMaxDynamicSharedMemorySize, GSMEM);
    cudaFuncSetAttribute(mma_gemm<1,2>, cudaFuncAttributeMaxDynamicSharedMemorySize, GSMEM);
    cudaFuncSetAttribute(mma_gemm<0,0>, cudaFuncAttributeMaxDynamicSharedMemorySize, GSMEM);
    cudaFuncSetAttribute(cg_kernel,     cudaFuncAttributeMaxDynamicSharedMemorySize, CGSMEM);

    prep_kernel<<<1, 32>>>(scale_gain, skip_w, coupling);

    wtrans_kernel<<<dim3(N3D/32, DD/32), 256>>>(Wqkv,  p_wqkvT,  DD, N3D);
    wtrans_kernel<<<dim3(DD/32,  DD/32), 256>>>(Wgate, p_wgateT, DD, DD);
    wtrans_kernel<<<dim3(DD/32,  DD/32), 256>>>(Wout,  p_woutT,  DD, DD);
    tohalf_kernel<<<(MTOT*DD/4)/256, 256>>>(x, p_xh);

    // GEMM1: qkv = x @ Wqkv + bqkv  (split: q->half, k->sumsq partials, v->half)
    mma_gemm<0,1><<<dim3(N3D/128, MTOT/128), 256, GSMEM>>>(
        p_xh, p_wqkvT, bqkv, nullptr, 0, DD);
    // GEMM2: gate = sigmoid(q @ Wgate + bgate) -> half
    mma_gemm<1,2><<<dim3(DD/128, MTOT/128), 256, GSMEM>>>(
        p_qh, p_wgateT, bgate, nullptr, 0, DD);

    field_kernel  <<<dim3(NN/32, BB*HH), 256>>>();
    pyramid_kernel<<<BB*HH*HD, 256>>>();
    cg_kernel     <<<dim3(NN/16, BB), 256, CGSMEM>>>();

    // GEMM3: out = pre @ Wout + bout
    mma_gemm<0,0><<<dim3(DD/128, MTOT/128), 256, GSMEM>>>(
        p_preh, p_woutT, bout, out, DD, DD);
}